// round 1
// baseline (speedup 1.0000x reference)
#include <cuda_runtime.h>
#include <math.h>

// ---------------- problem constants ----------------
#define T_SEQ 1000
#define BATCH 16
#define HID   256
#define M_ROWS (BATCH * T_SEQ)   // 16000
#define NBLK  64                 // blocks per LSTM direction

// ---------------- scratch (device globals; no cudaMalloc allowed) ----------
__device__ float g_h1 [M_ROWS * 1024];
__device__ float g_h2 [M_ROWS * 2560];
__device__ float g_xgf[M_ROWS * 1024];
__device__ float g_xgb[M_ROWS * 1024];
__device__ float g_out0[M_ROWS * 512];
__device__ float g_out1[M_ROWS * 512];
__device__ float g_hbuf[2 * 2 * 4096];   // [dir][parity][16*256]
__device__ unsigned g_barctr[2];

// ---------------- SGEMM: C[M,N] = A[M,K] @ B[N,K]^T + bias1 (+bias2), opt ReLU
// A row-major lda=K, B row-major (weights [N,K]). M%128==0, N%128==0, K%16==0.
__global__ __launch_bounds__(256) void sgemm128(
    const float* __restrict__ A, const float* __restrict__ Bw,
    const float* __restrict__ bias1, const float* __restrict__ bias2,
    float* __restrict__ C, int M, int N, int K, int relu)
{
    __shared__ float As[16][128];
    __shared__ float Bs[16][128];

    const int tid = threadIdx.x;
    const int tx = tid & 15;          // 0..15 (N microtile)
    const int ty = tid >> 4;          // 0..15 (M microtile)
    const int rowBase = blockIdx.y * 128;
    const int colBase = blockIdx.x * 128;

    float acc[8][8];
    #pragma unroll
    for (int i = 0; i < 8; i++)
        #pragma unroll
        for (int j = 0; j < 8; j++) acc[i][j] = 0.f;

    for (int k0 = 0; k0 < K; k0 += 16) {
        // load 128x16 tiles of A and B (512 float4 each, 2 per thread)
        #pragma unroll
        for (int l = 0; l < 2; l++) {
            int id = tid + l * 256;          // 0..511
            int r  = id >> 2;                // 0..127
            int kq = (id & 3) << 2;          // 0,4,8,12
            float4 a = *(const float4*)&A[(size_t)(rowBase + r) * K + k0 + kq];
            As[kq + 0][r] = a.x; As[kq + 1][r] = a.y;
            As[kq + 2][r] = a.z; As[kq + 3][r] = a.w;
            float4 b = *(const float4*)&Bw[(size_t)(colBase + r) * K + k0 + kq];
            Bs[kq + 0][r] = b.x; Bs[kq + 1][r] = b.y;
            Bs[kq + 2][r] = b.z; Bs[kq + 3][r] = b.w;
        }
        __syncthreads();

        #pragma unroll
        for (int k = 0; k < 16; k++) {
            float ra[8], rb[8];
            *(float4*)&ra[0] = *(const float4*)&As[k][ty * 8];
            *(float4*)&ra[4] = *(const float4*)&As[k][ty * 8 + 4];
            *(float4*)&rb[0] = *(const float4*)&Bs[k][tx * 8];
            *(float4*)&rb[4] = *(const float4*)&Bs[k][tx * 8 + 4];
            #pragma unroll
            for (int i = 0; i < 8; i++)
                #pragma unroll
                for (int j = 0; j < 8; j++)
                    acc[i][j] = fmaf(ra[i], rb[j], acc[i][j]);
        }
        __syncthreads();
    }

    // epilogue
    float bv[8];
    #pragma unroll
    for (int j = 0; j < 8; j++) {
        int n = colBase + tx * 8 + j;
        bv[j] = bias1[n] + (bias2 ? bias2[n] : 0.f);
    }
    #pragma unroll
    for (int i = 0; i < 8; i++) {
        int r = rowBase + ty * 8 + i;
        #pragma unroll
        for (int j4 = 0; j4 < 2; j4++) {
            float4 v;
            v.x = acc[i][j4 * 4 + 0] + bv[j4 * 4 + 0];
            v.y = acc[i][j4 * 4 + 1] + bv[j4 * 4 + 1];
            v.z = acc[i][j4 * 4 + 2] + bv[j4 * 4 + 2];
            v.w = acc[i][j4 * 4 + 3] + bv[j4 * 4 + 3];
            if (relu) {
                v.x = fmaxf(v.x, 0.f); v.y = fmaxf(v.y, 0.f);
                v.z = fmaxf(v.z, 0.f); v.w = fmaxf(v.w, 0.f);
            }
            *(float4*)&C[(size_t)r * N + colBase + tx * 8 + j4 * 4] = v;
        }
    }
}

// ---------------- init: zero barrier counters + h double buffers -----------
__global__ void init_rec_kernel()
{
    int t = blockIdx.x * blockDim.x + threadIdx.x;
    if (t < 2) g_barctr[t] = 0u;
    if (t < 2 * 2 * 4096) g_hbuf[t] = 0.f;
}

// ---------------- persistent bidirectional LSTM recurrence -----------------
// grid = 128 blocks: [0,64) forward, [64,128) backward. Each block owns 4
// hidden units (16 gate cols x 16 batches = 256 dot products/step).
__global__ __launch_bounds__(256) void lstm_rec_kernel(
    const float* __restrict__ xg_f, const float* __restrict__ xg_b,
    const float* __restrict__ whh_f, const float* __restrict__ whh_b,
    float* __restrict__ out)
{
    const int dir   = blockIdx.x / NBLK;          // 0 fwd, 1 bwd
    const int blk   = blockIdx.x % NBLK;
    const int jbase = blk * 4;                    // hidden-unit base
    const int tid   = threadIdx.x;
    const int b     = tid >> 4;                   // batch 0..15
    const int col   = tid & 15;                   // local gate col 0..15
    const int gate  = col >> 2;                   // 0..3 (i,f,g,o)
    const int jl    = col & 3;
    const int xgcol = gate * 256 + jbase + jl;

    const float* xg  = dir ? xg_b  : xg_f;
    const float* whh = dir ? whh_b : whh_f;

    __shared__ float wsm[16][260];   // [local col][k], padded
    __shared__ float hsm[16][260];   // [batch][k], padded
    __shared__ float gsm[16][16];    // raw gates [batch][local col]

    // load W_hh slice: rows (gate*256 + jbase + jl) of [1024,256]
    for (int i = tid; i < 16 * 256; i += 256) {
        int c = i >> 8, k = i & 255;
        int g2 = c >> 2, j2 = c & 3;
        wsm[c][k] = whh[(g2 * 256 + jbase + j2) * 256 + k];
    }

    float cst = 0.f;                        // cell state, held by tid<64
    const int ub = tid >> 2, uj = tid & 3;  // update mapping
    float* hbuf = g_hbuf + dir * 2 * 4096;
    unsigned* ctr = &g_barctr[dir];
    __syncthreads();

    for (int iter = 0; iter < T_SEQ; iter++) {
        const int par = iter & 1;
        // load h_prev [16,256] from global (L2, other SMs wrote it) into smem
        {
            const float4* src = (const float4*)(hbuf + par * 4096);
            #pragma unroll
            for (int i = 0; i < 4; i++) {
                int id = tid * 4 + i;              // float4 index 0..1023
                float4 v = __ldcg(&src[id]);       // bypass (stale) L1
                int bb = id >> 6;
                int kk = (id & 63) << 2;
                *(float4*)&hsm[bb][kk] = v;
            }
        }
        __syncthreads();

        const int t = dir ? (T_SEQ - 1 - iter) : iter;
        float xv = __ldg(&xg[(size_t)(b * T_SEQ + t) * 1024 + xgcol]);

        float acc = 0.f;
        const float4* wr = (const float4*)&wsm[col][0];
        const float4* hr = (const float4*)&hsm[b][0];
        #pragma unroll 8
        for (int k4 = 0; k4 < 64; k4++) {
            float4 w = wr[k4];
            float4 h = hr[k4];
            acc = fmaf(w.x, h.x, acc);
            acc = fmaf(w.y, h.y, acc);
            acc = fmaf(w.z, h.z, acc);
            acc = fmaf(w.w, h.w, acc);
        }
        gsm[b][col] = acc + xv;
        __syncthreads();

        if (tid < 64) {
            float gi = gsm[ub][0  + uj];
            float gf = gsm[ub][4  + uj];
            float gg = gsm[ub][8  + uj];
            float go = gsm[ub][12 + uj];
            float si = 1.f / (1.f + expf(-gi));
            float sf = 1.f / (1.f + expf(-gf));
            float tg = tanhf(gg);
            float so = 1.f / (1.f + expf(-go));
            cst = sf * cst + si * tg;
            float hv = so * tanhf(cst);
            hbuf[(par ^ 1) * 4096 + ub * 256 + jbase + uj] = hv;
            out[(size_t)(ub * T_SEQ + t) * 512 + dir * 256 + jbase + uj] = hv;
            __threadfence();
        }
        __syncthreads();

        if (tid == 0) {
            atomicAdd(ctr, 1u);
            unsigned target = (unsigned)(iter + 1) * NBLK;
            while (*((volatile unsigned*)ctr) < target) { __nanosleep(32); }
        }
        __syncthreads();
        __threadfence();
    }
}

// ---------------- final FC: [16000,512] @ [29,512]^T + b -------------------
__global__ __launch_bounds__(256) void fc_kernel(
    const float* __restrict__ A, const float* __restrict__ W,
    const float* __restrict__ bias, float* __restrict__ out)
{
    __shared__ float as[8][512];
    int r0 = blockIdx.x * 8;
    for (int i = threadIdx.x; i < 8 * 512; i += 256)
        as[i >> 9][i & 511] = A[(size_t)(r0 + (i >> 9)) * 512 + (i & 511)];
    __syncthreads();

    int r = threadIdx.x >> 5;       // 0..7
    int c = threadIdx.x & 31;       // 0..31
    if (c < 29) {
        const float* w = W + c * 512;
        float acc = 0.f;
        #pragma unroll 8
        for (int k = 0; k < 512; k++) acc = fmaf(as[r][k], __ldg(&w[k]), acc);
        out[(size_t)(r0 + r) * 29 + c] = acc + bias[c];
    }
}

// ---------------- launch ---------------------------------------------------
extern "C" void kernel_launch(void* const* d_in, const int* in_sizes, int n_in,
                              void* d_out, int out_size)
{
    (void)in_sizes; (void)n_in; (void)out_size;
    const float* x        = (const float*)d_in[0];
    const float* fe_w1    = (const float*)d_in[1];
    const float* fe_b1    = (const float*)d_in[2];
    const float* fe_w2    = (const float*)d_in[3];
    const float* fe_b2    = (const float*)d_in[4];
    const float* w_ih_l0f = (const float*)d_in[5];
    const float* w_hh_l0f = (const float*)d_in[6];
    const float* b_ih_l0f = (const float*)d_in[7];
    const float* b_hh_l0f = (const float*)d_in[8];
    const float* w_ih_l0b = (const float*)d_in[9];
    const float* w_hh_l0b = (const float*)d_in[10];
    const float* b_ih_l0b = (const float*)d_in[11];
    const float* b_hh_l0b = (const float*)d_in[12];
    const float* w_ih_l1f = (const float*)d_in[13];
    const float* w_hh_l1f = (const float*)d_in[14];
    const float* b_ih_l1f = (const float*)d_in[15];
    const float* b_hh_l1f = (const float*)d_in[16];
    const float* w_ih_l1b = (const float*)d_in[17];
    const float* w_hh_l1b = (const float*)d_in[18];
    const float* b_ih_l1b = (const float*)d_in[19];
    const float* b_hh_l1b = (const float*)d_in[20];
    const float* fc_w     = (const float*)d_in[21];
    const float* fc_b     = (const float*)d_in[22];
    float* out = (float*)d_out;

    float *h1, *h2, *xgf, *xgb, *o0, *o1;
    cudaGetSymbolAddress((void**)&h1,  g_h1);
    cudaGetSymbolAddress((void**)&h2,  g_h2);
    cudaGetSymbolAddress((void**)&xgf, g_xgf);
    cudaGetSymbolAddress((void**)&xgb, g_xgb);
    cudaGetSymbolAddress((void**)&o0,  g_out0);
    cudaGetSymbolAddress((void**)&o1,  g_out1);

    // feature extractor
    sgemm128<<<dim3(1024 / 128, M_ROWS / 128), 256>>>(x,  fe_w1, fe_b1, nullptr, h1, M_ROWS, 1024, 80,   1);
    sgemm128<<<dim3(2560 / 128, M_ROWS / 128), 256>>>(h1, fe_w2, fe_b2, nullptr, h2, M_ROWS, 2560, 1024, 1);

    // layer 0: input-gate precompute + bidirectional recurrence
    sgemm128<<<dim3(8, M_ROWS / 128), 256>>>(h2, w_ih_l0f, b_ih_l0f, b_hh_l0f, xgf, M_ROWS, 1024, 2560, 0);
    sgemm128<<<dim3(8, M_ROWS / 128), 256>>>(h2, w_ih_l0b, b_ih_l0b, b_hh_l0b, xgb, M_ROWS, 1024, 2560, 0);
    init_rec_kernel<<<64, 256>>>();
    lstm_rec_kernel<<<2 * NBLK, 256>>>(xgf, xgb, w_hh_l0f, w_hh_l0b, o0);

    // layer 1
    sgemm128<<<dim3(8, M_ROWS / 128), 256>>>(o0, w_ih_l1f, b_ih_l1f, b_hh_l1f, xgf, M_ROWS, 1024, 512, 0);
    sgemm128<<<dim3(8, M_ROWS / 128), 256>>>(o0, w_ih_l1b, b_ih_l1b, b_hh_l1b, xgb, M_ROWS, 1024, 512, 0);
    init_rec_kernel<<<64, 256>>>();
    lstm_rec_kernel<<<2 * NBLK, 256>>>(xgf, xgb, w_hh_l1f, w_hh_l1b, o1);

    // classifier
    fc_kernel<<<M_ROWS / 8, 256>>>(o1, fc_w, fc_b, out);
}

// round 4
// speedup vs baseline: 1.1606x; 1.1606x over previous
#include <cuda_runtime.h>
#include <cstdint>
#include <math.h>

// ---------------- problem constants ----------------
#define T_SEQ 1000
#define BATCH 16
#define M_ROWS (BATCH * T_SEQ)   // 16000
#define NBLK  64                 // blocks per LSTM direction

// ---------------- scratch (device globals; no cudaMalloc allowed) ----------
__device__ float g_h1 [M_ROWS * 1024];
__device__ float g_h2 [(size_t)M_ROWS * 2560];
__device__ float g_xgf[M_ROWS * 1024];
__device__ float g_xgb[M_ROWS * 1024];
__device__ float g_out0[M_ROWS * 512];
__device__ float g_out1[M_ROWS * 512];
__device__ float g_hbuf[2 * 2 * 4096];   // [dir][parity][16*256]
__device__ unsigned g_barctr[2];

// ================= PTX helpers =================
__device__ __forceinline__ uint32_t smem_u32(const void* p) {
    uint32_t a;
    asm("{ .reg .u64 t; cvta.to.shared.u64 t, %1; cvt.u32.u64 %0, t; }" : "=r"(a) : "l"(p));
    return a;
}
__device__ __forceinline__ void cpa16(uint32_t dst, const void* src) {
    asm volatile("cp.async.cg.shared.global [%0], [%1], 16;" :: "r"(dst), "l"(src) : "memory");
}
__device__ __forceinline__ void sts_zero16(uint32_t dst) {
    asm volatile("st.shared.v4.b32 [%0], {%1,%1,%1,%1};" :: "r"(dst), "r"(0u) : "memory");
}
#define CP_COMMIT() asm volatile("cp.async.commit_group;" ::: "memory")
#define CP_WAIT1()  asm volatile("cp.async.wait_group 1;" ::: "memory")
#define CP_WAIT0()  asm volatile("cp.async.wait_group 0;" ::: "memory")

__device__ __forceinline__ void ldsm4(uint32_t addr, uint32_t& r0, uint32_t& r1,
                                      uint32_t& r2, uint32_t& r3) {
    asm volatile("ldmatrix.sync.aligned.m8n8.x4.shared.b16 {%0,%1,%2,%3}, [%4];"
                 : "=r"(r0), "=r"(r1), "=r"(r2), "=r"(r3) : "r"(addr));
}
__device__ __forceinline__ void mma_tf32(float* d, const uint32_t* a, const uint32_t* b) {
    asm volatile(
        "mma.sync.aligned.m16n8k8.row.col.f32.tf32.tf32.f32 "
        "{%0,%1,%2,%3}, {%4,%5,%6,%7}, {%8,%9}, {%0,%1,%2,%3};"
        : "+f"(d[0]), "+f"(d[1]), "+f"(d[2]), "+f"(d[3])
        : "r"(a[0]), "r"(a[1]), "r"(a[2]), "r"(a[3]), "r"(b[0]), "r"(b[1]));
}
// split fp32 (bit pattern in v) into tf32 hi + tf32 lo, hi+lo ~= v to ~2^-22
__device__ __forceinline__ void tf32_split(uint32_t v, uint32_t& hi, uint32_t& lo) {
    float f = __uint_as_float(v);
    asm("cvt.rna.tf32.f32 %0, %1;" : "=r"(hi) : "f"(f));
    float r = f - __uint_as_float(hi);
    asm("cvt.rna.tf32.f32 %0, %1;" : "=r"(lo) : "f"(r));
}

// ================= tensor-core 3xTF32 GEMM (mma.sync path) =================
// C[M,N] = A[M,K] @ Bw[N,K]^T + bias1 (+bias2), optional ReLU.
// 128x128 CTA tile, 8 warps in 2(m)x4(n), warp tile 64x32.
// K-chunk 32, 2-stage cp.async double buffer.
// fp32 emulation: acc += Alo*Bhi + Ahi*Blo + Ahi*Bhi (3 MMAs per fragment pair).
// SMEM tiles: rows padded to 36 floats (144B) -> ldmatrix conflict-free.
#define ROWB   144
#define TILEB  (128 * ROWB)          // 18432 per operand
#define STAGEB (2 * TILEB)           // 36864 per stage (A + B)
#define GEMM_SMEM_BYTES (1024 + 2 * STAGEB)

__global__ __launch_bounds__(256)
void tc_gemm(const float* __restrict__ A, const float* __restrict__ Bw,
             const float* __restrict__ bias1, const float* __restrict__ bias2,
             float* __restrict__ C, int M, int N, int K, int relu)
{
    extern __shared__ __align__(1024) char smem[];
    const int tid = threadIdx.x;
    const int wid = tid >> 5;
    const int lid = tid & 31;
    const int wm  = wid & 1;          // 0..1 (m)
    const int wn  = wid >> 1;         // 0..3 (n)
    const uint32_t sbase = smem_u32(smem);
    float* bsm = (float*)(smem);      // 128 floats bias
    const uint32_t tiles = sbase + 1024;

    const int rowBase = blockIdx.y * 128;
    const int colBase = blockIdx.x * 128;

    if (tid < 128) bsm[tid] = bias1[colBase + tid] + (bias2 ? bias2[colBase + tid] : 0.f);

    float acc[4][4][4];
    #pragma unroll
    for (int i = 0; i < 4; i++)
        #pragma unroll
        for (int j = 0; j < 4; j++)
            #pragma unroll
            for (int q = 0; q < 4; q++) acc[i][j][q] = 0.f;

    const int NC = (K + 31) / 32;

    // chunk loader: A 1024 granules + B 1024 granules (16B each), 8/thread
    auto load_chunk = [&](int stage, int k0) {
        uint32_t abase = tiles + stage * STAGEB;
        uint32_t bbase = abase + TILEB;
        #pragma unroll
        for (int i = 0; i < 8; i++) {
            int id  = tid + (i << 8);
            int row = (id >> 3) & 127;
            int g   = id & 7;
            int k   = k0 + (g << 2);
            if (id < 1024) {
                uint32_t dst = abase + row * ROWB + (g << 4);
                if (k < K) cpa16(dst, A + (size_t)(rowBase + row) * K + k);
                else       sts_zero16(dst);
            } else {
                uint32_t dst = bbase + row * ROWB + (g << 4);
                if (k < K) cpa16(dst, Bw + (size_t)(colBase + row) * K + k);
                else       sts_zero16(dst);
            }
        }
    };

    load_chunk(0, 0);
    CP_COMMIT();

    for (int c = 0; c < NC; c++) {
        if (c + 1 < NC) { load_chunk((c + 1) & 1, (c + 1) * 32); CP_COMMIT(); CP_WAIT1(); }
        else            { CP_WAIT0(); }
        __syncthreads();

        uint32_t abase = tiles + (c & 1) * STAGEB;
        uint32_t bbase = abase + TILEB;
        const int lm = lid >> 3;            // which sub-matrix this thread addresses
        const int lr = lid & 7;

        #pragma unroll
        for (int ks = 0; ks < 4; ks++) {
            uint32_t ah[4][4], al[4][4], bh[4][2], bl[4][2];
            // A fragments: 4 m16 tiles
            #pragma unroll
            for (int mt = 0; mt < 4; mt++) {
                uint32_t raw[4];
                uint32_t r = wm * 64 + mt * 16 + ((lm & 1) << 3) + lr;
                uint32_t addr = abase + r * ROWB + (ks << 5) + ((lm >> 1) << 4);
                ldsm4(addr, raw[0], raw[1], raw[2], raw[3]);
                #pragma unroll
                for (int q = 0; q < 4; q++) tf32_split(raw[q], ah[mt][q], al[mt][q]);
            }
            // B fragments: 2 x4 loads cover 4 n8 tiles
            #pragma unroll
            for (int bt = 0; bt < 2; bt++) {
                uint32_t raw[4];
                uint32_t r = wn * 32 + bt * 16 + ((lm >> 1) << 3) + lr;
                uint32_t addr = bbase + r * ROWB + (ks << 5) + ((lm & 1) << 4);
                ldsm4(addr, raw[0], raw[1], raw[2], raw[3]);
                tf32_split(raw[0], bh[2 * bt][0],     bl[2 * bt][0]);
                tf32_split(raw[1], bh[2 * bt][1],     bl[2 * bt][1]);
                tf32_split(raw[2], bh[2 * bt + 1][0], bl[2 * bt + 1][0]);
                tf32_split(raw[3], bh[2 * bt + 1][1], bl[2 * bt + 1][1]);
            }
            #pragma unroll
            for (int mt = 0; mt < 4; mt++)
                #pragma unroll
                for (int nt = 0; nt < 4; nt++) {
                    mma_tf32(acc[mt][nt], al[mt], bh[nt]);
                    mma_tf32(acc[mt][nt], ah[mt], bl[nt]);
                    mma_tf32(acc[mt][nt], ah[mt], bh[nt]);
                }
        }
        __syncthreads();
    }

    // epilogue: c0:(g,2tg) c1:(g,2tg+1) c2:(g+8,2tg) c3:(g+8,2tg+1)
    const int g  = lid >> 2;
    const int tg = lid & 3;
    #pragma unroll
    for (int mt = 0; mt < 4; mt++) {
        int r0 = rowBase + wm * 64 + mt * 16 + g;
        #pragma unroll
        for (int nt = 0; nt < 4; nt++) {
            int cc = wn * 32 + nt * 8 + 2 * tg;
            float b0 = bsm[cc], b1 = bsm[cc + 1];
            float2 v0 = make_float2(acc[mt][nt][0] + b0, acc[mt][nt][1] + b1);
            float2 v1 = make_float2(acc[mt][nt][2] + b0, acc[mt][nt][3] + b1);
            if (relu) {
                v0.x = fmaxf(v0.x, 0.f); v0.y = fmaxf(v0.y, 0.f);
                v1.x = fmaxf(v1.x, 0.f); v1.y = fmaxf(v1.y, 0.f);
            }
            *(float2*)&C[(size_t)r0 * N + colBase + cc] = v0;
            *(float2*)&C[(size_t)(r0 + 8) * N + colBase + cc] = v1;
        }
    }
}

// ---------------- init: zero barrier counters + h double buffers -----------
__global__ void init_rec_kernel()
{
    int t = blockIdx.x * blockDim.x + threadIdx.x;
    if (t < 2) g_barctr[t] = 0u;
    if (t < 2 * 2 * 4096) g_hbuf[t] = 0.f;
}

// ---------------- persistent bidirectional LSTM recurrence -----------------
__global__ __launch_bounds__(256) void lstm_rec_kernel(
    const float* __restrict__ xg_f, const float* __restrict__ xg_b,
    const float* __restrict__ whh_f, const float* __restrict__ whh_b,
    float* __restrict__ out)
{
    const int dir   = blockIdx.x / NBLK;
    const int blk   = blockIdx.x % NBLK;
    const int jbase = blk * 4;
    const int tid   = threadIdx.x;
    const int b     = tid >> 4;
    const int col   = tid & 15;
    const int gate  = col >> 2;
    const int jl    = col & 3;
    const int xgcol = gate * 256 + jbase + jl;

    const float* xg  = dir ? xg_b  : xg_f;
    const float* whh = dir ? whh_b : whh_f;

    __shared__ float wsm[16][260];
    __shared__ float hsm[16][260];
    __shared__ float gsm[16][16];

    for (int i = tid; i < 16 * 256; i += 256) {
        int c = i >> 8, k = i & 255;
        int g2 = c >> 2, j2 = c & 3;
        wsm[c][k] = whh[(g2 * 256 + jbase + j2) * 256 + k];
    }

    float cst = 0.f;
    const int ub = tid >> 2, uj = tid & 3;
    float* hbuf = g_hbuf + dir * 2 * 4096;
    unsigned* ctr = &g_barctr[dir];
    __syncthreads();

    for (int iter = 0; iter < T_SEQ; iter++) {
        const int par = iter & 1;
        {
            const float4* src = (const float4*)(hbuf + par * 4096);
            #pragma unroll
            for (int i = 0; i < 4; i++) {
                int id = tid * 4 + i;
                float4 v = __ldcg(&src[id]);
                int bb = id >> 6;
                int kk = (id & 63) << 2;
                *(float4*)&hsm[bb][kk] = v;
            }
        }
        __syncthreads();

        const int t = dir ? (T_SEQ - 1 - iter) : iter;
        float xv = __ldg(&xg[(size_t)(b * T_SEQ + t) * 1024 + xgcol]);

        float acc = 0.f;
        const float4* wr = (const float4*)&wsm[col][0];
        const float4* hr = (const float4*)&hsm[b][0];
        #pragma unroll 8
        for (int k4 = 0; k4 < 64; k4++) {
            float4 w = wr[k4];
            float4 h = hr[k4];
            acc = fmaf(w.x, h.x, acc);
            acc = fmaf(w.y, h.y, acc);
            acc = fmaf(w.z, h.z, acc);
            acc = fmaf(w.w, h.w, acc);
        }
        gsm[b][col] = acc + xv;
        __syncthreads();

        if (tid < 64) {
            float gi = gsm[ub][0  + uj];
            float gf = gsm[ub][4  + uj];
            float gg = gsm[ub][8  + uj];
            float go = gsm[ub][12 + uj];
            float si = 1.f / (1.f + expf(-gi));
            float sf = 1.f / (1.f + expf(-gf));
            float tg = tanhf(gg);
            float so = 1.f / (1.f + expf(-go));
            cst = sf * cst + si * tg;
            float hv = so * tanhf(cst);
            hbuf[(par ^ 1) * 4096 + ub * 256 + jbase + uj] = hv;
            out[(size_t)(ub * T_SEQ + t) * 512 + dir * 256 + jbase + uj] = hv;
            __threadfence();
        }
        __syncthreads();

        if (tid == 0) {
            atomicAdd(ctr, 1u);
            unsigned target = (unsigned)(iter + 1) * NBLK;
            while (*((volatile unsigned*)ctr) < target) { __nanosleep(32); }
        }
        __syncthreads();
        __threadfence();
    }
}

// ---------------- final FC: [16000,512] @ [29,512]^T + b -------------------
__global__ __launch_bounds__(256) void fc_kernel(
    const float* __restrict__ A, const float* __restrict__ W,
    const float* __restrict__ bias, float* __restrict__ out)
{
    __shared__ float as[8][512];
    int r0 = blockIdx.x * 8;
    for (int i = threadIdx.x; i < 8 * 512; i += 256)
        as[i >> 9][i & 511] = A[(size_t)(r0 + (i >> 9)) * 512 + (i & 511)];
    __syncthreads();

    int r = threadIdx.x >> 5;
    int c = threadIdx.x & 31;
    if (c < 29) {
        const float* w = W + c * 512;
        float acc = 0.f;
        #pragma unroll 8
        for (int k = 0; k < 512; k++) acc = fmaf(as[r][k], __ldg(&w[k]), acc);
        out[(size_t)(r0 + r) * 29 + c] = acc + bias[c];
    }
}

// ---------------- launch ---------------------------------------------------
extern "C" void kernel_launch(void* const* d_in, const int* in_sizes, int n_in,
                              void* d_out, int out_size)
{
    (void)in_sizes; (void)n_in; (void)out_size;
    const float* x        = (const float*)d_in[0];
    const float* fe_w1    = (const float*)d_in[1];
    const float* fe_b1    = (const float*)d_in[2];
    const float* fe_w2    = (const float*)d_in[3];
    const float* fe_b2    = (const float*)d_in[4];
    const float* w_ih_l0f = (const float*)d_in[5];
    const float* w_hh_l0f = (const float*)d_in[6];
    const float* b_ih_l0f = (const float*)d_in[7];
    const float* b_hh_l0f = (const float*)d_in[8];
    const float* w_ih_l0b = (const float*)d_in[9];
    const float* w_hh_l0b = (const float*)d_in[10];
    const float* b_ih_l0b = (const float*)d_in[11];
    const float* b_hh_l0b = (const float*)d_in[12];
    const float* w_ih_l1f = (const float*)d_in[13];
    const float* w_hh_l1f = (const float*)d_in[14];
    const float* b_ih_l1f = (const float*)d_in[15];
    const float* b_hh_l1f = (const float*)d_in[16];
    const float* w_ih_l1b = (const float*)d_in[17];
    const float* w_hh_l1b = (const float*)d_in[18];
    const float* b_ih_l1b = (const float*)d_in[19];
    const float* b_hh_l1b = (const float*)d_in[20];
    const float* fc_w     = (const float*)d_in[21];
    const float* fc_b     = (const float*)d_in[22];
    float* out = (float*)d_out;

    float *h1, *h2, *xgf, *xgb, *o0, *o1;
    cudaGetSymbolAddress((void**)&h1,  g_h1);
    cudaGetSymbolAddress((void**)&h2,  g_h2);
    cudaGetSymbolAddress((void**)&xgf, g_xgf);
    cudaGetSymbolAddress((void**)&xgb, g_xgb);
    cudaGetSymbolAddress((void**)&o0,  g_out0);
    cudaGetSymbolAddress((void**)&o1,  g_out1);

    cudaFuncSetAttribute(tc_gemm, cudaFuncAttributeMaxDynamicSharedMemorySize, GEMM_SMEM_BYTES);

    // feature extractor
    tc_gemm<<<dim3(1024 / 128, M_ROWS / 128), 256, GEMM_SMEM_BYTES>>>(x,  fe_w1, fe_b1, nullptr, h1, M_ROWS, 1024, 80,   1);
    tc_gemm<<<dim3(2560 / 128, M_ROWS / 128), 256, GEMM_SMEM_BYTES>>>(h1, fe_w2, fe_b2, nullptr, h2, M_ROWS, 2560, 1024, 1);

    // layer 0: input-gate precompute + bidirectional recurrence
    tc_gemm<<<dim3(8, M_ROWS / 128), 256, GEMM_SMEM_BYTES>>>(h2, w_ih_l0f, b_ih_l0f, b_hh_l0f, xgf, M_ROWS, 1024, 2560, 0);
    tc_gemm<<<dim3(8, M_ROWS / 128), 256, GEMM_SMEM_BYTES>>>(h2, w_ih_l0b, b_ih_l0b, b_hh_l0b, xgb, M_ROWS, 1024, 2560, 0);
    init_rec_kernel<<<64, 256>>>();
    lstm_rec_kernel<<<2 * NBLK, 256>>>(xgf, xgb, w_hh_l0f, w_hh_l0b, o0);

    // layer 1
    tc_gemm<<<dim3(8, M_ROWS / 128), 256, GEMM_SMEM_BYTES>>>(o0, w_ih_l1f, b_ih_l1f, b_hh_l1f, xgf, M_ROWS, 1024, 512, 0);
    tc_gemm<<<dim3(8, M_ROWS / 128), 256, GEMM_SMEM_BYTES>>>(o0, w_ih_l1b, b_ih_l1b, b_hh_l1b, xgb, M_ROWS, 1024, 512, 0);
    init_rec_kernel<<<64, 256>>>();
    lstm_rec_kernel<<<2 * NBLK, 256>>>(xgf, xgb, w_hh_l1f, w_hh_l1b, o1);

    // classifier
    fc_kernel<<<M_ROWS / 8, 256>>>(o1, fc_w, fc_b, out);
}